// round 6
// baseline (speedup 1.0000x reference)
#include <cuda_runtime.h>
#include <cuda_bf16.h>
#include <cstdint>

#define B_    32
#define T_    512
#define H_    256
#define WDIM_ 300

typedef unsigned long long u64;

// ---------------- scratch (device globals; no allocation allowed) ----------------
__device__ __align__(16) __nv_bfloat16 g_zhi[16384 * 256];       // z split hi  [r][k]
__device__ __align__(16) __nv_bfloat16 g_zlo[16384 * 256];       // z split lo  [r][k]
__device__ __align__(16) __nv_bfloat16 g_wt[2][2][1024][256];    // [dir][part][c][k]
__device__ __align__(16) float g_gates[2 * 512 * 1024 * 32];     // [dir][t][col][b] 128 MB
__device__ __align__(16) __nv_bfloat16 g_hx[2][2][32 * 512];     // [buf][dir][b][hi(256)|lo(256)]
__device__ __align__(16) float g_hsum[512 * 32];                 // [feat][b]
__device__ __align__(16) float g_fc[256 * 32];                   // [j][b]
__device__ unsigned g_arrive[2];
__device__ unsigned g_gen[2];
__device__ __align__(128) unsigned g_flags[2][64];               // monotonic publish counters

// ---------------- f32x2 helpers (exact fp32 semantics; used in k1) ----------------
__device__ __forceinline__ u64 pk(float lo, float hi) {
    u64 r; asm("mov.b64 %0, {%1, %2};" : "=l"(r) : "f"(lo), "f"(hi)); return r;
}
__device__ __forceinline__ u64 dupf(float v) {
    u64 r; asm("mov.b64 %0, {%1, %1};" : "=l"(r) : "f"(v)); return r;
}
__device__ __forceinline__ void fma2(u64& d, u64 a, u64 b) {
    asm("fma.rn.f32x2 %0, %1, %2, %0;" : "+l"(d) : "l"(a), "l"(b));
}
__device__ __forceinline__ float2 upk(u64 v) {
    float2 f; asm("mov.b64 {%0, %1}, %2;" : "=f"(f.x), "=f"(f.y) : "l"(v)); return f;
}

__device__ __forceinline__ float sigf(float x) { return 1.0f / (1.0f + __expf(-x)); }

__device__ __forceinline__ unsigned ldacq(const unsigned* p) {
    unsigned v;
    asm volatile("ld.acquire.gpu.global.u32 %0, [%1];" : "=r"(v) : "l"(p) : "memory");
    return v;
}
__device__ __forceinline__ void red_release_add1(unsigned* p) {
    asm volatile("red.release.gpu.global.add.u32 [%0], 1;" :: "l"(p) : "memory");
}

// warp-level bf16 MMA (sm_80+ baseline; works on compute_103)
__device__ __forceinline__ void mma16816(float* c, const unsigned* a, unsigned b0, unsigned b1) {
    asm volatile(
        "mma.sync.aligned.m16n8k16.row.col.f32.bf16.bf16.f32 "
        "{%0,%1,%2,%3}, {%4,%5,%6,%7}, {%8,%9}, {%0,%1,%2,%3};"
        : "+f"(c[0]), "+f"(c[1]), "+f"(c[2]), "+f"(c[3])
        : "r"(a[0]), "r"(a[1]), "r"(a[2]), "r"(a[3]), "r"(b0), "r"(b1));
}

// Sense-reversing barrier among the 64 CTAs of one direction (used ONCE at start of k3).
__device__ __forceinline__ void dir_barrier(int dir, unsigned ncta) {
    __syncthreads();
    if (threadIdx.x == 0) {
        volatile unsigned* gen = &g_gen[dir];
        unsigned old = *gen;
        __threadfence();
        unsigned a = atomicAdd(&g_arrive[dir], 1u);
        if (a == ncta - 1u) {
            g_arrive[dir] = 0u;
            __threadfence();
            atomicExch((unsigned*)&g_gen[dir], old + 1u);
        } else {
            while (*gen == old) { }
        }
        __threadfence();
    }
    __syncthreads();
}

// ---------------- kernel 1: z = relu(emb[x] @ W_in + b_in) -> bf16 hi/lo ----------------
__global__ void k1_embed(const float* __restrict__ emb, const float* __restrict__ Win,
                         const float* __restrict__ bin, const int* __restrict__ x) {
    __shared__ float As[12][68];
    __shared__ float Bs[12][68];
    __shared__ int   xid[64];
    int tid = threadIdx.x;
    int r0 = blockIdx.x * 64;
    int c0 = blockIdx.y * 64;
    if (tid < 64) {
        int r = r0 + tid;
        int b = r & 31, t = r >> 5;
        xid[tid] = x[b * T_ + t];
    }
    __syncthreads();
    int tx = tid & 15, ty = tid >> 4;
    u64 acc2[2][4];
#pragma unroll
    for (int p = 0; p < 2; ++p)
#pragma unroll
        for (int j = 0; j < 4; ++j) acc2[p][j] = 0ULL;

    int ar = tid >> 2, ag = (tid & 3) * 3;
    int bc = tid & 63, bg = (tid >> 6) * 3;

    for (int k0 = 0; k0 < WDIM_; k0 += 12) {
        const float* ep = emb + (size_t)xid[ar] * WDIM_ + k0 + ag;
        As[ag + 0][ar] = ep[0];
        As[ag + 1][ar] = ep[1];
        As[ag + 2][ar] = ep[2];
#pragma unroll
        for (int j = 0; j < 3; ++j)
            Bs[bg + j][bc] = Win[(size_t)(k0 + bg + j) * H_ + c0 + bc];
        __syncthreads();
#pragma unroll
        for (int kk = 0; kk < 12; ++kk) {
            float4 a  = *(const float4*)&As[kk][ty * 4];
            float4 bv = *(const float4*)&Bs[kk][tx * 4];
            u64 ap0 = pk(a.x, a.y), ap1 = pk(a.z, a.w);
            u64 bd0 = dupf(bv.x), bd1 = dupf(bv.y), bd2 = dupf(bv.z), bd3 = dupf(bv.w);
            fma2(acc2[0][0], ap0, bd0); fma2(acc2[0][1], ap0, bd1);
            fma2(acc2[0][2], ap0, bd2); fma2(acc2[0][3], ap0, bd3);
            fma2(acc2[1][0], ap1, bd0); fma2(acc2[1][1], ap1, bd1);
            fma2(acc2[1][2], ap1, bd2); fma2(acc2[1][3], ap1, bd3);
        }
        __syncthreads();
    }
    float bj[4];
#pragma unroll
    for (int j = 0; j < 4; ++j) bj[j] = bin[c0 + tx * 4 + j];
#pragma unroll
    for (int p = 0; p < 2; ++p) {
        float2 uu[4];
#pragma unroll
        for (int j = 0; j < 4; ++j) uu[j] = upk(acc2[p][j]);
        float vr[2][4];
#pragma unroll
        for (int j = 0; j < 4; ++j) {
            vr[0][j] = fmaxf(uu[j].x + bj[j], 0.0f);
            vr[1][j] = fmaxf(uu[j].y + bj[j], 0.0f);
        }
#pragma unroll
        for (int q = 0; q < 2; ++q) {
            int r = r0 + ty * 4 + p * 2 + q;
            size_t base = (size_t)r * 256 + c0 + tx * 4;
            __nv_bfloat16 h[4], l[4];
#pragma unroll
            for (int j = 0; j < 4; ++j) {
                h[j] = __float2bfloat16(vr[q][j]);
                l[j] = __float2bfloat16(vr[q][j] - __bfloat162float(h[j]));
            }
            *(__nv_bfloat162*)&g_zhi[base]     = __nv_bfloat162{h[0], h[1]};
            *(__nv_bfloat162*)&g_zhi[base + 2] = __nv_bfloat162{h[2], h[3]};
            *(__nv_bfloat162*)&g_zlo[base]     = __nv_bfloat162{l[0], l[1]};
            *(__nv_bfloat162*)&g_zlo[base + 2] = __nv_bfloat162{l[2], l[3]};
        }
    }
}

// ---------------- kernel 2w: split/transpose Wih -> g_wt[dir][part][c][k] ----------------
__global__ void k2w_conv(const float* __restrict__ Wf, const float* __restrict__ Wb) {
    int gid = blockIdx.x * 256 + threadIdx.x;     // 2*1024*256 total
    int k = gid & 255;
    int c = (gid >> 8) & 1023;
    int dir = gid >> 18;
    float w = (dir ? Wb : Wf)[(size_t)k * 1024 + c];
    __nv_bfloat16 hi = __float2bfloat16(w);
    __nv_bfloat16 lo = __float2bfloat16(w - __bfloat162float(hi));
    g_wt[dir][0][c][k] = hi;
    g_wt[dir][1][c][k] = lo;
}

// ---------------- kernel 2: HMMA bf16-split GEMM: gates = z @ Wih + bl ----------------
#define AS_STRIDE 72
__global__ void __launch_bounds__(256) k2_hmma(const float* __restrict__ blf,
                                               const float* __restrict__ blb) {
    __shared__ __align__(16) unsigned char smraw[2 * 128 * AS_STRIDE * 2];
    __nv_bfloat16* As = (__nv_bfloat16*)smraw;                       // [128][72]
    __nv_bfloat16* Bs = As + 128 * AS_STRIDE;                        // [128][72]
    float* Sc = (float*)smraw;                                       // epilogue: [8 warps][8][33]

    int tid = threadIdx.x;
    int wid = tid >> 5, lane = tid & 31;
    int g = lane >> 2, tg = lane & 3;
    int wm = wid & 3, wn = wid >> 2;
    int bx = blockIdx.x, by = blockIdx.y;
    int dir = by >> 3;
    int c0  = (by & 7) * 128;
    int r0  = bx * 128;

    int lrow = tid >> 1;
    int lhalf = tid & 1;

    float c[2][8][4];
#pragma unroll
    for (int mi = 0; mi < 2; ++mi)
#pragma unroll
        for (int ni = 0; ni < 8; ++ni)
#pragma unroll
            for (int q = 0; q < 4; ++q) c[mi][ni][q] = 0.0f;

    int m0 = wm * 32;
    int n0 = wn * 64;

    for (int seg = 0; seg < 3; ++seg) {
        const __nv_bfloat16* Ag = (seg < 2) ? g_zhi : g_zlo;
        const __nv_bfloat16* Bg = &g_wt[dir][(seg == 1) ? 1 : 0][c0][0];

        for (int chunk = 0; chunk < 4; ++chunk) {
            int k0 = chunk * 64;
            {
                const uint4* src = (const uint4*)(Ag + (size_t)(r0 + lrow) * 256 + k0 + lhalf * 32);
                uint4* dst = (uint4*)(As + lrow * AS_STRIDE + lhalf * 32);
#pragma unroll
                for (int q = 0; q < 4; ++q) dst[q] = src[q];
            }
            {
                const uint4* src = (const uint4*)(Bg + (size_t)lrow * 256 + k0 + lhalf * 32);
                uint4* dst = (uint4*)(Bs + lrow * AS_STRIDE + lhalf * 32);
#pragma unroll
                for (int q = 0; q < 4; ++q) dst[q] = src[q];
            }
            __syncthreads();

#pragma unroll
            for (int ks = 0; ks < 4; ++ks) {
                int k1 = ks * 16;
                unsigned a[2][4];
#pragma unroll
                for (int mi = 0; mi < 2; ++mi) {
                    const __nv_bfloat16* ab = As + (m0 + mi * 16 + g) * AS_STRIDE + k1 + tg * 2;
                    a[mi][0] = *(const unsigned*)ab;
                    a[mi][1] = *(const unsigned*)(ab + 8 * AS_STRIDE);
                    a[mi][2] = *(const unsigned*)(ab + 8);
                    a[mi][3] = *(const unsigned*)(ab + 8 * AS_STRIDE + 8);
                }
#pragma unroll
                for (int ni = 0; ni < 8; ++ni) {
                    const __nv_bfloat16* bb = Bs + (n0 + ni * 8 + g) * AS_STRIDE + k1 + tg * 2;
                    unsigned b0 = *(const unsigned*)bb;
                    unsigned b1 = *(const unsigned*)(bb + 8);
                    mma16816(c[0][ni], a[0], b0, b1);
                    mma16816(c[1][ni], a[1], b0, b1);
                }
            }
            __syncthreads();
        }
    }

    const float* bl = dir ? blb : blf;
    int t = bx * 4 + wm;
    float* myS = Sc + wid * (8 * 33);
    size_t gbase = (size_t)(dir * 512 + t) * (1024 * 32);
#pragma unroll
    for (int ni = 0; ni < 8; ++ni) {
#pragma unroll
        for (int mi = 0; mi < 2; ++mi)
#pragma unroll
            for (int q = 0; q < 4; ++q) {
                int col_local = tg * 2 + (q & 1);
                int row_local = mi * 16 + g + ((q >> 1) ? 8 : 0);
                myS[col_local * 33 + row_local] = c[mi][ni][q];
            }
        __syncwarp();
#pragma unroll
        for (int col = 0; col < 8; ++col) {
            int cg = c0 + n0 + ni * 8 + col;
            float v = myS[col * 33 + lane] + __ldg(&bl[cg]);
            g_gates[gbase + (size_t)cg * 32 + lane] = v;
        }
        __syncwarp();
    }
}

// ---------------- kernel 3: persistent BiLSTM recurrence with HMMA ----------------
// 128 CTAs: dir = cta>>6, slice = cta&63 owns hidden units [slice*4, slice*4+4).
// Per step: h published as bf16 hi/lo split; z = h @ Whh_slice via m16n8k16 bf16 MMA
// (3 terms: hi*Whi + lo*Whi + hi*Wlo), Whh B-fragments persistent in registers.
#define AST 520   // As stride in bf16 elements (word stride 260 -> banks 4g+tg, conflict-free)
__global__ void __launch_bounds__(256, 1)
k3_lstm(const float* __restrict__ Whhf, const float* __restrict__ Whhb,
        const int* __restrict__ mask) {
    __shared__ __align__(16) __nv_bfloat16 As[32 * AST];   // 33280 B; [b][ hi(256) | lo(256) ]
    float* red = (float*)As;                               // aliased: 8 * 528 floats

    int cta   = blockIdx.x;
    int dir   = cta >> 6;
    int slice = cta & 63;
    int u0    = slice << 2;
    const float* Whh = dir ? Whhb : Whhf;
    int tid  = threadIdx.x;
    int warp = tid >> 5, lane = tid & 31;
    int g = lane >> 2, tg = lane & 3;
    int kbase = warp * 32;          // this warp's K slice [kbase, kbase+32)

    // persistent B fragments: bhi/blo[kt][nt][r]  (n = nt*8+g, k = kbase+kt*16+tg*2+r*8)
    unsigned bhi[2][2][2], blo[2][2][2];
#pragma unroll
    for (int kt = 0; kt < 2; ++kt)
#pragma unroll
        for (int nt = 0; nt < 2; ++nt)
#pragma unroll
            for (int r = 0; r < 2; ++r) {
                int n  = nt * 8 + g;                     // local col 0..15
                int gc = (n >> 2) * 256 + u0 + (n & 3);  // global gate col
                int k  = kbase + kt * 16 + tg * 2 + r * 8;
                float w0 = Whh[(size_t)k * 1024 + gc];
                float w1 = Whh[(size_t)(k + 1) * 1024 + gc];
                __nv_bfloat16 h0 = __float2bfloat16(w0);
                __nv_bfloat16 h1 = __float2bfloat16(w1);
                __nv_bfloat16 l0 = __float2bfloat16(w0 - __bfloat162float(h0));
                __nv_bfloat16 l1 = __float2bfloat16(w1 - __bfloat162float(h1));
                __nv_bfloat162 ph{h0, h1}, pl{l0, l1};
                bhi[kt][nt][r] = *(unsigned*)&ph;
                blo[kt][nt][r] = *(unsigned*)&pl;
            }

    int u = tid >> 5;        // valid for tid < 128
    int b = tid & 31;
    float c_reg = 0.0f, h_reg = 0.0f, hsum_reg = 0.0f;
    if (tid < 128) {
        g_hx[0][dir][b * 512 + u0 + u]       = __float2bfloat16(0.0f);
        g_hx[0][dir][b * 512 + 256 + u0 + u] = __float2bfloat16(0.0f);
    }

    unsigned base = 0;
    const unsigned* myflag = 0;
    if (tid >= 192) {
        myflag = &g_flags[dir][tid - 192];
        base = ldacq(myflag);
    }
    dir_barrier(dir, 64);    // zeros + base reads complete before any publish

    unsigned* pubflag = &g_flags[dir][slice];
    int crow = tid >> 3;            // copy: row 0..31
    int ck   = (tid & 7) * 64;      // 64 bf16 (8 uint4) per thread

    for (int t = 0; t < T_; ++t) {
        int cur = t & 1, nxt = cur ^ 1;
        int tt = dir ? (T_ - 1 - t) : t;

        // prefetch gate preactivations + mask (independent of h; in flight during spin)
        float gpre0 = 0.f, gpre1 = 0.f, gpre2 = 0.f, gpre3 = 0.f, mval = 0.f;
        if (tid < 128) {
            const float* gp = g_gates + (size_t)(dir * 512 + tt) * (1024 * 32);
            gpre0 = gp[(0 * 256 + u0 + u) * 32 + b];
            gpre1 = gp[(1 * 256 + u0 + u) * 32 + b];
            gpre2 = gp[(2 * 256 + u0 + u) * 32 + b];
            gpre3 = gp[(3 * 256 + u0 + u) * 32 + b];
            mval  = (float)mask[b * T_ + tt];
        }

        // wait for all 64 producers (each step adds 128 per flag)
        if (tid >= 192) {
            unsigned need = 128u * (unsigned)t;
            while (ldacq(myflag) - base < need) { }
        }
        __syncthreads();   // also protects red (gates finished reading) before As overwrite

        // copy h split into smem As[b][kext]
        {
            const uint4* src = (const uint4*)(&g_hx[cur][dir][0] + crow * 512 + ck);
            uint4* dst = (uint4*)(As + crow * AST + ck);
#pragma unroll
            for (int q = 0; q < 8; ++q) dst[q] = __ldcg(src + q);
        }
        __syncthreads();

        // z partial: 3-term bf16 split MMA over this warp's k slice
        float c[2][2][4];
#pragma unroll
        for (int mi = 0; mi < 2; ++mi)
#pragma unroll
            for (int ni = 0; ni < 2; ++ni)
#pragma unroll
                for (int q = 0; q < 4; ++q) c[mi][ni][q] = 0.0f;

        unsigned afr[2][2][4];
        // A = hi  (offset 0)
#pragma unroll
        for (int kt = 0; kt < 2; ++kt)
#pragma unroll
            for (int mi = 0; mi < 2; ++mi) {
                const __nv_bfloat16* ab = As + (mi * 16 + g) * AST + kbase + kt * 16 + tg * 2;
                afr[kt][mi][0] = *(const unsigned*)ab;
                afr[kt][mi][1] = *(const unsigned*)(ab + 8 * AST);
                afr[kt][mi][2] = *(const unsigned*)(ab + 8);
                afr[kt][mi][3] = *(const unsigned*)(ab + 8 * AST + 8);
            }
#pragma unroll
        for (int kt = 0; kt < 2; ++kt)
#pragma unroll
            for (int mi = 0; mi < 2; ++mi)
#pragma unroll
                for (int ni = 0; ni < 2; ++ni) {
                    mma16816(c[mi][ni], afr[kt][mi], bhi[kt][ni][0], bhi[kt][ni][1]);  // hi*Whi
                    mma16816(c[mi][ni], afr[kt][mi], blo[kt][ni][0], blo[kt][ni][1]);  // hi*Wlo
                }
        // A = lo  (offset 256)
#pragma unroll
        for (int kt = 0; kt < 2; ++kt)
#pragma unroll
            for (int mi = 0; mi < 2; ++mi) {
                const __nv_bfloat16* ab = As + (mi * 16 + g) * AST + 256 + kbase + kt * 16 + tg * 2;
                afr[kt][mi][0] = *(const unsigned*)ab;
                afr[kt][mi][1] = *(const unsigned*)(ab + 8 * AST);
                afr[kt][mi][2] = *(const unsigned*)(ab + 8);
                afr[kt][mi][3] = *(const unsigned*)(ab + 8 * AST + 8);
            }
#pragma unroll
        for (int kt = 0; kt < 2; ++kt)
#pragma unroll
            for (int mi = 0; mi < 2; ++mi)
#pragma unroll
                for (int ni = 0; ni < 2; ++ni)
                    mma16816(c[mi][ni], afr[kt][mi], bhi[kt][ni][0], bhi[kt][ni][1]);  // lo*Whi

        __syncthreads();   // all fragment reads of As done before red (alias) writes
#pragma unroll
        for (int mi = 0; mi < 2; ++mi)
#pragma unroll
            for (int ni = 0; ni < 2; ++ni)
#pragma unroll
                for (int q = 0; q < 4; ++q) {
                    int row = mi * 16 + g + ((q >> 1) ? 8 : 0);
                    int col = ni * 8 + tg * 2 + (q & 1);
                    red[warp * 528 + col * 33 + row] = c[mi][ni][q];
                }
        __syncthreads();

        if (tid < 128) {
            float z0 = gpre0, z1 = gpre1, z2 = gpre2, z3 = gpre3;
#pragma unroll
            for (int w = 0; w < 8; ++w) {
                const float* rp = red + w * 528 + b;
                z0 += rp[(0 + u) * 33];
                z1 += rp[(4 + u) * 33];
                z2 += rp[(8 + u) * 33];
                z3 += rp[(12 + u) * 33];
            }
            float ig = sigf(z0), fg = sigf(z1);
            float gg = tanhf(z2), og = sigf(z3);
            float cn = fg * c_reg + ig * gg;
            float hn = og * tanhf(cn);
            c_reg = mval * cn + (1.0f - mval) * c_reg;
            h_reg = mval * hn + (1.0f - mval) * h_reg;
            hsum_reg += mval * h_reg;
            __nv_bfloat16 hh = __float2bfloat16(h_reg);
            __nv_bfloat16 hl = __float2bfloat16(h_reg - __bfloat162float(hh));
            g_hx[nxt][dir][b * 512 + u0 + u]       = hh;
            g_hx[nxt][dir][b * 512 + 256 + u0 + u] = hl;
            red_release_add1(pubflag);   // release orders this thread's stores
        }
    }
    if (tid < 128) g_hsum[((dir << 8) + u0 + u) * 32 + b] = hsum_reg;
}

// ---------------- kernel 4a: fc_hidden[j][b], one CTA per j ----------------
__global__ void k4a_fc(const float* __restrict__ Wfc, const float* __restrict__ bfc,
                       const int* __restrict__ lengths) {
    __shared__ float redsm[8][32];
    int j = blockIdx.x;
    int tid = threadIdx.x;
    int w = tid >> 5, lane = tid & 31;
    float acc = 0.0f;
    int f0 = w * 64;
#pragma unroll 8
    for (int f = f0; f < f0 + 64; ++f)
        acc += g_hsum[f * 32 + lane] * Wfc[(size_t)f * 256 + j];
    redsm[w][lane] = acc;
    __syncthreads();
    if (w == 0) {
        float s = 0.0f;
#pragma unroll
        for (int q = 0; q < 8; ++q) s += redsm[q][lane];
        float invlen = 1.0f / (float)lengths[lane];
        g_fc[j * 32 + lane] = fmaxf(s * invlen + bfc[j], 0.0f);
    }
}

// ---------------- kernel 4b: logits ----------------
__global__ void k4b_out(const float* __restrict__ Wout, const float* __restrict__ bout,
                        float* __restrict__ out) {
    int t = threadIdx.x;
    int b = t >> 1, lab = t & 1;
    float s = bout[lab];
#pragma unroll 8
    for (int j = 0; j < 256; ++j)
        s += g_fc[j * 32 + b] * Wout[j * 2 + lab];
    out[b * 2 + lab] = s;
}

// ---------------- launch ----------------
extern "C" void kernel_launch(void* const* d_in, const int* in_sizes, int n_in,
                              void* d_out, int out_size) {
    const float* emb  = (const float*)d_in[0];
    const float* Win  = (const float*)d_in[1];
    const float* bin  = (const float*)d_in[2];
    const float* Wihf = (const float*)d_in[3];
    const float* Whhf = (const float*)d_in[4];
    const float* blf  = (const float*)d_in[5];
    const float* Wihb = (const float*)d_in[6];
    const float* Whhb = (const float*)d_in[7];
    const float* blb  = (const float*)d_in[8];
    const float* Wfc  = (const float*)d_in[9];
    const float* bfc  = (const float*)d_in[10];
    const float* Wout = (const float*)d_in[11];
    const float* bout = (const float*)d_in[12];
    const int*   x    = (const int*)d_in[13];
    const int*   mask = (const int*)d_in[14];
    const int*   len  = (const int*)d_in[15];
    float* out = (float*)d_out;

    k1_embed<<<dim3(256, 4), 256>>>(emb, Win, bin, x);
    k2w_conv<<<2048, 256>>>(Wihf, Wihb);
    k2_hmma<<<dim3(128, 16), 256>>>(blf, blb);
    k3_lstm<<<128, 256>>>(Whhf, Whhb, mask);
    k4a_fc<<<256, 256>>>(Wfc, bfc, len);
    k4b_out<<<1, 64>>>(Wout, bout, out);
}

// round 7
// speedup vs baseline: 1.1031x; 1.1031x over previous
#include <cuda_runtime.h>
#include <cuda_bf16.h>
#include <cstdint>

#define B_    32
#define T_    512
#define H_    256
#define WDIM_ 300

typedef unsigned long long u64;

// ---------------- scratch (device globals; no allocation allowed) ----------------
__device__ __align__(16) __nv_bfloat16 g_zhi[16384 * 256];       // z split hi  [r][k]
__device__ __align__(16) __nv_bfloat16 g_zlo[16384 * 256];       // z split lo  [r][k]
__device__ __align__(16) __nv_bfloat16 g_wt[2][2][1024][256];    // [dir][part][c][k]
__device__ __align__(16) float g_gates[2 * 512 * 1024 * 32];     // [dir][t][col][b] 128 MB
__device__ __align__(16) unsigned g_hp[2][2][32][256];           // [buf][dir][b][hi pairs 128 | lo pairs 128]
__device__ __align__(16) float g_hsum[512 * 32];                 // [feat][b]
__device__ __align__(16) float g_fc[256 * 32];                   // [j][b]
__device__ unsigned g_arrive[2];
__device__ unsigned g_gen[2];
__device__ __align__(128) unsigned g_flags[2][64];               // monotonic publish counters

// ---------------- f32x2 helpers (exact fp32 semantics; used in k1) ----------------
__device__ __forceinline__ u64 pk(float lo, float hi) {
    u64 r; asm("mov.b64 %0, {%1, %2};" : "=l"(r) : "f"(lo), "f"(hi)); return r;
}
__device__ __forceinline__ u64 dupf(float v) {
    u64 r; asm("mov.b64 %0, {%1, %1};" : "=l"(r) : "f"(v)); return r;
}
__device__ __forceinline__ void fma2(u64& d, u64 a, u64 b) {
    asm("fma.rn.f32x2 %0, %1, %2, %0;" : "+l"(d) : "l"(a), "l"(b));
}
__device__ __forceinline__ float2 upk(u64 v) {
    float2 f; asm("mov.b64 {%0, %1}, %2;" : "=f"(f.x), "=f"(f.y) : "l"(v)); return f;
}

__device__ __forceinline__ float sigf(float x) { return 1.0f / (1.0f + __expf(-x)); }

__device__ __forceinline__ unsigned ldacq(const unsigned* p) {
    unsigned v;
    asm volatile("ld.acquire.gpu.global.u32 %0, [%1];" : "=r"(v) : "l"(p) : "memory");
    return v;
}
__device__ __forceinline__ void red_release_add1(unsigned* p) {
    asm volatile("red.release.gpu.global.add.u32 [%0], 1;" :: "l"(p) : "memory");
}

// warp-level bf16 MMA (sm_80+ baseline; works on compute_103)
__device__ __forceinline__ void mma16816(float* c, const unsigned* a, unsigned b0, unsigned b1) {
    asm volatile(
        "mma.sync.aligned.m16n8k16.row.col.f32.bf16.bf16.f32 "
        "{%0,%1,%2,%3}, {%4,%5,%6,%7}, {%8,%9}, {%0,%1,%2,%3};"
        : "+f"(c[0]), "+f"(c[1]), "+f"(c[2]), "+f"(c[3])
        : "r"(a[0]), "r"(a[1]), "r"(a[2]), "r"(a[3]), "r"(b0), "r"(b1));
}

// Sense-reversing barrier among the 64 CTAs of one direction (used ONCE at start of k3).
__device__ __forceinline__ void dir_barrier(int dir, unsigned ncta) {
    __syncthreads();
    if (threadIdx.x == 0) {
        volatile unsigned* gen = &g_gen[dir];
        unsigned old = *gen;
        __threadfence();
        unsigned a = atomicAdd(&g_arrive[dir], 1u);
        if (a == ncta - 1u) {
            g_arrive[dir] = 0u;
            __threadfence();
            atomicExch((unsigned*)&g_gen[dir], old + 1u);
        } else {
            while (*gen == old) { }
        }
        __threadfence();
    }
    __syncthreads();
}

// ---------------- kernel 1: z = relu(emb[x] @ W_in + b_in) -> bf16 hi/lo ----------------
__global__ void k1_embed(const float* __restrict__ emb, const float* __restrict__ Win,
                         const float* __restrict__ bin, const int* __restrict__ x) {
    __shared__ float As[12][68];
    __shared__ float Bs[12][68];
    __shared__ int   xid[64];
    int tid = threadIdx.x;
    int r0 = blockIdx.x * 64;
    int c0 = blockIdx.y * 64;
    if (tid < 64) {
        int r = r0 + tid;
        int b = r & 31, t = r >> 5;
        xid[tid] = x[b * T_ + t];
    }
    __syncthreads();
    int tx = tid & 15, ty = tid >> 4;
    u64 acc2[2][4];
#pragma unroll
    for (int p = 0; p < 2; ++p)
#pragma unroll
        for (int j = 0; j < 4; ++j) acc2[p][j] = 0ULL;

    int ar = tid >> 2, ag = (tid & 3) * 3;
    int bc = tid & 63, bg = (tid >> 6) * 3;

    for (int k0 = 0; k0 < WDIM_; k0 += 12) {
        const float* ep = emb + (size_t)xid[ar] * WDIM_ + k0 + ag;
        As[ag + 0][ar] = ep[0];
        As[ag + 1][ar] = ep[1];
        As[ag + 2][ar] = ep[2];
#pragma unroll
        for (int j = 0; j < 3; ++j)
            Bs[bg + j][bc] = Win[(size_t)(k0 + bg + j) * H_ + c0 + bc];
        __syncthreads();
#pragma unroll
        for (int kk = 0; kk < 12; ++kk) {
            float4 a  = *(const float4*)&As[kk][ty * 4];
            float4 bv = *(const float4*)&Bs[kk][tx * 4];
            u64 ap0 = pk(a.x, a.y), ap1 = pk(a.z, a.w);
            u64 bd0 = dupf(bv.x), bd1 = dupf(bv.y), bd2 = dupf(bv.z), bd3 = dupf(bv.w);
            fma2(acc2[0][0], ap0, bd0); fma2(acc2[0][1], ap0, bd1);
            fma2(acc2[0][2], ap0, bd2); fma2(acc2[0][3], ap0, bd3);
            fma2(acc2[1][0], ap1, bd0); fma2(acc2[1][1], ap1, bd1);
            fma2(acc2[1][2], ap1, bd2); fma2(acc2[1][3], ap1, bd3);
        }
        __syncthreads();
    }
    float bj[4];
#pragma unroll
    for (int j = 0; j < 4; ++j) bj[j] = bin[c0 + tx * 4 + j];
#pragma unroll
    for (int p = 0; p < 2; ++p) {
        float2 uu[4];
#pragma unroll
        for (int j = 0; j < 4; ++j) uu[j] = upk(acc2[p][j]);
        float vr[2][4];
#pragma unroll
        for (int j = 0; j < 4; ++j) {
            vr[0][j] = fmaxf(uu[j].x + bj[j], 0.0f);
            vr[1][j] = fmaxf(uu[j].y + bj[j], 0.0f);
        }
#pragma unroll
        for (int q = 0; q < 2; ++q) {
            int r = r0 + ty * 4 + p * 2 + q;
            size_t base = (size_t)r * 256 + c0 + tx * 4;
            __nv_bfloat16 h[4], l[4];
#pragma unroll
            for (int j = 0; j < 4; ++j) {
                h[j] = __float2bfloat16(vr[q][j]);
                l[j] = __float2bfloat16(vr[q][j] - __bfloat162float(h[j]));
            }
            *(__nv_bfloat162*)&g_zhi[base]     = __nv_bfloat162{h[0], h[1]};
            *(__nv_bfloat162*)&g_zhi[base + 2] = __nv_bfloat162{h[2], h[3]};
            *(__nv_bfloat162*)&g_zlo[base]     = __nv_bfloat162{l[0], l[1]};
            *(__nv_bfloat162*)&g_zlo[base + 2] = __nv_bfloat162{l[2], l[3]};
        }
    }
}

// ---------------- kernel 2w: split/transpose Wih -> g_wt[dir][part][c][k] ----------------
__global__ void k2w_conv(const float* __restrict__ Wf, const float* __restrict__ Wb) {
    int gid = blockIdx.x * 256 + threadIdx.x;     // 2*1024*256 total
    int k = gid & 255;
    int c = (gid >> 8) & 1023;
    int dir = gid >> 18;
    float w = (dir ? Wb : Wf)[(size_t)k * 1024 + c];
    __nv_bfloat16 hi = __float2bfloat16(w);
    __nv_bfloat16 lo = __float2bfloat16(w - __bfloat162float(hi));
    g_wt[dir][0][c][k] = hi;
    g_wt[dir][1][c][k] = lo;
}

// ---------------- kernel 2: HMMA bf16-split GEMM: gates = z @ Wih + bl ----------------
#define AS_STRIDE 72
__global__ void __launch_bounds__(256) k2_hmma(const float* __restrict__ blf,
                                               const float* __restrict__ blb) {
    __shared__ __align__(16) unsigned char smraw[2 * 128 * AS_STRIDE * 2];
    __nv_bfloat16* As = (__nv_bfloat16*)smraw;                       // [128][72]
    __nv_bfloat16* Bs = As + 128 * AS_STRIDE;                        // [128][72]
    float* Sc = (float*)smraw;                                       // epilogue: [8 warps][8][33]

    int tid = threadIdx.x;
    int wid = tid >> 5, lane = tid & 31;
    int g = lane >> 2, tg = lane & 3;
    int wm = wid & 3, wn = wid >> 2;
    int bx = blockIdx.x, by = blockIdx.y;
    int dir = by >> 3;
    int c0  = (by & 7) * 128;
    int r0  = bx * 128;

    int lrow = tid >> 1;
    int lhalf = tid & 1;

    float c[2][8][4];
#pragma unroll
    for (int mi = 0; mi < 2; ++mi)
#pragma unroll
        for (int ni = 0; ni < 8; ++ni)
#pragma unroll
            for (int q = 0; q < 4; ++q) c[mi][ni][q] = 0.0f;

    int m0 = wm * 32;
    int n0 = wn * 64;

    for (int seg = 0; seg < 3; ++seg) {
        const __nv_bfloat16* Ag = (seg < 2) ? g_zhi : g_zlo;
        const __nv_bfloat16* Bg = &g_wt[dir][(seg == 1) ? 1 : 0][c0][0];

        for (int chunk = 0; chunk < 4; ++chunk) {
            int k0 = chunk * 64;
            {
                const uint4* src = (const uint4*)(Ag + (size_t)(r0 + lrow) * 256 + k0 + lhalf * 32);
                uint4* dst = (uint4*)(As + lrow * AS_STRIDE + lhalf * 32);
#pragma unroll
                for (int q = 0; q < 4; ++q) dst[q] = src[q];
            }
            {
                const uint4* src = (const uint4*)(Bg + (size_t)lrow * 256 + k0 + lhalf * 32);
                uint4* dst = (uint4*)(Bs + lrow * AS_STRIDE + lhalf * 32);
#pragma unroll
                for (int q = 0; q < 4; ++q) dst[q] = src[q];
            }
            __syncthreads();

#pragma unroll
            for (int ks = 0; ks < 4; ++ks) {
                int k1 = ks * 16;
                unsigned a[2][4];
#pragma unroll
                for (int mi = 0; mi < 2; ++mi) {
                    const __nv_bfloat16* ab = As + (m0 + mi * 16 + g) * AS_STRIDE + k1 + tg * 2;
                    a[mi][0] = *(const unsigned*)ab;
                    a[mi][1] = *(const unsigned*)(ab + 8 * AS_STRIDE);
                    a[mi][2] = *(const unsigned*)(ab + 8);
                    a[mi][3] = *(const unsigned*)(ab + 8 * AS_STRIDE + 8);
                }
#pragma unroll
                for (int ni = 0; ni < 8; ++ni) {
                    const __nv_bfloat16* bb = Bs + (n0 + ni * 8 + g) * AS_STRIDE + k1 + tg * 2;
                    unsigned b0 = *(const unsigned*)bb;
                    unsigned b1 = *(const unsigned*)(bb + 8);
                    mma16816(c[0][ni], a[0], b0, b1);
                    mma16816(c[1][ni], a[1], b0, b1);
                }
            }
            __syncthreads();
        }
    }

    const float* bl = dir ? blb : blf;
    int t = bx * 4 + wm;
    float* myS = Sc + wid * (8 * 33);
    size_t gbase = (size_t)(dir * 512 + t) * (1024 * 32);
#pragma unroll
    for (int ni = 0; ni < 8; ++ni) {
#pragma unroll
        for (int mi = 0; mi < 2; ++mi)
#pragma unroll
            for (int q = 0; q < 4; ++q) {
                int col_local = tg * 2 + (q & 1);
                int row_local = mi * 16 + g + ((q >> 1) ? 8 : 0);
                myS[col_local * 33 + row_local] = c[mi][ni][q];
            }
        __syncwarp();
#pragma unroll
        for (int col = 0; col < 8; ++col) {
            int cg = c0 + n0 + ni * 8 + col;
            float v = myS[col * 33 + lane] + __ldg(&bl[cg]);
            g_gates[gbase + (size_t)cg * 32 + lane] = v;
        }
        __syncwarp();
    }
}

// ---------------- kernel 3: persistent BiLSTM recurrence with HMMA ----------------
// 128 CTAs: dir = cta>>6, slice = cta&63 owns hidden units [slice*4, slice*4+4).
// h published as word-packed bf16 pairs: g_hp[buf][dir][b][j] = (hi_2j, hi_2j+1) for
// j<128, lo pairs at j>=128 -> bitwise same As layout as before, but stores are 8B.
#define AST   520   // As row stride in bf16 elements
#define AST_W 260   // = AST/2, in 32-bit words
__global__ void __launch_bounds__(256, 1)
k3_lstm(const float* __restrict__ Whhf, const float* __restrict__ Whhb,
        const int* __restrict__ mask) {
    __shared__ __align__(16) unsigned Asw[32 * AST_W];     // 33280 B
    __nv_bfloat16* As = (__nv_bfloat16*)Asw;               // [b][ hi(256) | lo(256) ] bf16
    float* red = (float*)Asw;                              // aliased: 8 * 528 floats (words 0..4223)
    unsigned* hbuf = Asw + 4224;                           // aliased: 128 words (after red)

    int cta   = blockIdx.x;
    int dir   = cta >> 6;
    int slice = cta & 63;
    int u0    = slice << 2;
    const float* Whh = dir ? Whhb : Whhf;
    int tid  = threadIdx.x;
    int warp = tid >> 5, lane = tid & 31;
    int g = lane >> 2, tg = lane & 3;
    int kbase = warp * 32;          // this warp's K slice [kbase, kbase+32)

    // persistent B fragments: bhi/blo[kt][nt][r]  (n = nt*8+g, k = kbase+kt*16+tg*2+r*8)
    unsigned bhi[2][2][2], blo[2][2][2];
#pragma unroll
    for (int kt = 0; kt < 2; ++kt)
#pragma unroll
        for (int nt = 0; nt < 2; ++nt)
#pragma unroll
            for (int r = 0; r < 2; ++r) {
                int n  = nt * 8 + g;
                int gc = (n >> 2) * 256 + u0 + (n & 3);
                int k  = kbase + kt * 16 + tg * 2 + r * 8;
                float w0 = Whh[(size_t)k * 1024 + gc];
                float w1 = Whh[(size_t)(k + 1) * 1024 + gc];
                __nv_bfloat16 h0 = __float2bfloat16(w0);
                __nv_bfloat16 h1 = __float2bfloat16(w1);
                __nv_bfloat16 l0 = __float2bfloat16(w0 - __bfloat162float(h0));
                __nv_bfloat16 l1 = __float2bfloat16(w1 - __bfloat162float(h1));
                __nv_bfloat162 ph{h0, h1}, pl{l0, l1};
                bhi[kt][nt][r] = *(unsigned*)&ph;
                blo[kt][nt][r] = *(unsigned*)&pl;
            }

    int u = tid >> 5;        // valid for tid < 128
    int b = tid & 31;
    float c_reg = 0.0f, h_reg = 0.0f, hsum_reg = 0.0f;
    if (tid < 32) {          // zero this CTA's h words (8B stores)
        uint2 z = make_uint2(0u, 0u);
        *(uint2*)&g_hp[0][dir][tid][slice * 2]       = z;
        *(uint2*)&g_hp[0][dir][tid][128 + slice * 2] = z;
    }

    unsigned base = 0;
    const unsigned* myflag = 0;
    if (tid >= 192) {
        myflag = &g_flags[dir][tid - 192];
        base = ldacq(myflag);
    }
    dir_barrier(dir, 64);    // zeros + base reads complete before any publish

    unsigned* pubflag = &g_flags[dir][slice];
    int crow = tid >> 3;            // copy: row b 0..31
    int ckw  = (tid & 7) * 32;      // 32 words (8 uint4) per thread

    for (int t = 0; t < T_; ++t) {
        int cur = t & 1, nxt = cur ^ 1;
        int tt = dir ? (T_ - 1 - t) : t;

        // prefetch gate preactivations + mask (in flight during spin)
        float gpre0 = 0.f, gpre1 = 0.f, gpre2 = 0.f, gpre3 = 0.f, mval = 0.f;
        if (tid < 128) {
            const float* gp = g_gates + (size_t)(dir * 512 + tt) * (1024 * 32);
            gpre0 = gp[(0 * 256 + u0 + u) * 32 + b];
            gpre1 = gp[(1 * 256 + u0 + u) * 32 + b];
            gpre2 = gp[(2 * 256 + u0 + u) * 32 + b];
            gpre3 = gp[(3 * 256 + u0 + u) * 32 + b];
            mval  = (float)mask[b * T_ + tt];
        }

        // wait: all 64 producers published (32 adds per CTA per step)
        if (tid >= 192) {
            unsigned need = 32u * (unsigned)t;
            while (ldacq(myflag) - base < need) { }
        }
        __syncthreads();   // also: gates finished reading red before As overwrite

        // copy h words into smem As
        {
            const uint4* src = (const uint4*)&g_hp[cur][dir][crow][ckw];
            uint4* dst = (uint4*)&Asw[crow * AST_W + ckw];
#pragma unroll
            for (int q = 0; q < 8; ++q) dst[q] = __ldcg(src + q);
        }
        __syncthreads();

        // z partial: 3-term bf16 split MMA over this warp's k slice
        float c[2][2][4];
#pragma unroll
        for (int mi = 0; mi < 2; ++mi)
#pragma unroll
            for (int ni = 0; ni < 2; ++ni)
#pragma unroll
                for (int q = 0; q < 4; ++q) c[mi][ni][q] = 0.0f;

        unsigned afr[2][2][4];
        // A = hi  (bf16 offset 0)
#pragma unroll
        for (int kt = 0; kt < 2; ++kt)
#pragma unroll
            for (int mi = 0; mi < 2; ++mi) {
                const __nv_bfloat16* ab = As + (mi * 16 + g) * AST + kbase + kt * 16 + tg * 2;
                afr[kt][mi][0] = *(const unsigned*)ab;
                afr[kt][mi][1] = *(const unsigned*)(ab + 8 * AST);
                afr[kt][mi][2] = *(const unsigned*)(ab + 8);
                afr[kt][mi][3] = *(const unsigned*)(ab + 8 * AST + 8);
            }
#pragma unroll
        for (int kt = 0; kt < 2; ++kt)
#pragma unroll
            for (int mi = 0; mi < 2; ++mi)
#pragma unroll
                for (int ni = 0; ni < 2; ++ni) {
                    mma16816(c[mi][ni], afr[kt][mi], bhi[kt][ni][0], bhi[kt][ni][1]);  // hi*Whi
                    mma16816(c[mi][ni], afr[kt][mi], blo[kt][ni][0], blo[kt][ni][1]);  // hi*Wlo
                }
        // A = lo  (bf16 offset 256)
#pragma unroll
        for (int kt = 0; kt < 2; ++kt)
#pragma unroll
            for (int mi = 0; mi < 2; ++mi) {
                const __nv_bfloat16* ab = As + (mi * 16 + g) * AST + 256 + kbase + kt * 16 + tg * 2;
                afr[kt][mi][0] = *(const unsigned*)ab;
                afr[kt][mi][1] = *(const unsigned*)(ab + 8 * AST);
                afr[kt][mi][2] = *(const unsigned*)(ab + 8);
                afr[kt][mi][3] = *(const unsigned*)(ab + 8 * AST + 8);
            }
#pragma unroll
        for (int kt = 0; kt < 2; ++kt)
#pragma unroll
            for (int mi = 0; mi < 2; ++mi)
#pragma unroll
                for (int ni = 0; ni < 2; ++ni)
                    mma16816(c[mi][ni], afr[kt][mi], bhi[kt][ni][0], bhi[kt][ni][1]);  // lo*Whi

        __syncthreads();   // all fragment reads of As done before red (alias) writes
#pragma unroll
        for (int mi = 0; mi < 2; ++mi)
#pragma unroll
            for (int ni = 0; ni < 2; ++ni)
#pragma unroll
                for (int q = 0; q < 4; ++q) {
                    int row = mi * 16 + g + ((q >> 1) ? 8 : 0);
                    int col = ni * 8 + tg * 2 + (q & 1);
                    red[warp * 528 + col * 33 + row] = c[mi][ni][q];
                }
        __syncthreads();

        if (tid < 128) {
            float z0 = gpre0, z1 = gpre1, z2 = gpre2, z3 = gpre3;
#pragma unroll
            for (int w = 0; w < 8; ++w) {
                const float* rp = red + w * 528 + b;
                z0 += rp[(0 + u) * 33];
                z1 += rp[(4 + u) * 33];
                z2 += rp[(8 + u) * 33];
                z3 += rp[(12 + u) * 33];
            }
            float ig = sigf(z0), fg = sigf(z1);
            float gg = tanhf(z2), og = sigf(z3);
            float cn = fg * c_reg + ig * gg;
            float hn = og * tanhf(cn);
            c_reg = mval * cn + (1.0f - mval) * c_reg;
            h_reg = mval * hn + (1.0f - mval) * h_reg;
            hsum_reg += mval * h_reg;
            __nv_bfloat16 hh = __float2bfloat16(h_reg);
            __nv_bfloat16 hl = __float2bfloat16(h_reg - __bfloat162float(hh));
            __nv_bfloat162 pw{hh, hl};
            hbuf[u * 32 + b] = *(unsigned*)&pw;     // (hi low16, lo high16)
        }
        __syncthreads();

        // warp 0: repack + publish with 8B stores, then release
        if (tid < 32) {
            unsigned w0 = hbuf[0 * 32 + tid];
            unsigned w1 = hbuf[1 * 32 + tid];
            unsigned w2 = hbuf[2 * 32 + tid];
            unsigned w3 = hbuf[3 * 32 + tid];
            unsigned hi01 = __byte_perm(w0, w1, 0x5410);
            unsigned hi23 = __byte_perm(w2, w3, 0x5410);
            unsigned lo01 = __byte_perm(w0, w1, 0x7632);
            unsigned lo23 = __byte_perm(w2, w3, 0x7632);
            *(uint2*)&g_hp[nxt][dir][tid][slice * 2]       = make_uint2(hi01, hi23);
            *(uint2*)&g_hp[nxt][dir][tid][128 + slice * 2] = make_uint2(lo01, lo23);
            red_release_add1(pubflag);   // release orders this thread's stores
        }
    }
    if (tid < 128) g_hsum[((dir << 8) + u0 + u) * 32 + b] = hsum_reg;
}

// ---------------- kernel 4a: fc_hidden[j][b], one CTA per j ----------------
__global__ void k4a_fc(const float* __restrict__ Wfc, const float* __restrict__ bfc,
                       const int* __restrict__ lengths) {
    __shared__ float redsm[8][32];
    int j = blockIdx.x;
    int tid = threadIdx.x;
    int w = tid >> 5, lane = tid & 31;
    float acc = 0.0f;
    int f0 = w * 64;
#pragma unroll 8
    for (int f = f0; f < f0 + 64; ++f)
        acc += g_hsum[f * 32 + lane] * Wfc[(size_t)f * 256 + j];
    redsm[w][lane] = acc;
    __syncthreads();
    if (w == 0) {
        float s = 0.0f;
#pragma unroll
        for (int q = 0; q < 8; ++q) s += redsm[q][lane];
        float invlen = 1.0f / (float)lengths[lane];
        g_fc[j * 32 + lane] = fmaxf(s * invlen + bfc[j], 0.0f);
    }
}

// ---------------- kernel 4b: logits ----------------
__global__ void k4b_out(const float* __restrict__ Wout, const float* __restrict__ bout,
                        float* __restrict__ out) {
    int t = threadIdx.x;
    int b = t >> 1, lab = t & 1;
    float s = bout[lab];
#pragma unroll 8
    for (int j = 0; j < 256; ++j)
        s += g_fc[j * 32 + b] * Wout[j * 2 + lab];
    out[b * 2 + lab] = s;
}

// ---------------- launch ----------------
extern "C" void kernel_launch(void* const* d_in, const int* in_sizes, int n_in,
                              void* d_out, int out_size) {
    const float* emb  = (const float*)d_in[0];
    const float* Win  = (const float*)d_in[1];
    const float* bin  = (const float*)d_in[2];
    const float* Wihf = (const float*)d_in[3];
    const float* Whhf = (const float*)d_in[4];
    const float* blf  = (const float*)d_in[5];
    const float* Wihb = (const float*)d_in[6];
    const float* Whhb = (const float*)d_in[7];
    const float* blb  = (const float*)d_in[8];
    const float* Wfc  = (const float*)d_in[9];
    const float* bfc  = (const float*)d_in[10];
    const float* Wout = (const float*)d_in[11];
    const float* bout = (const float*)d_in[12];
    const int*   x    = (const int*)d_in[13];
    const int*   mask = (const int*)d_in[14];
    const int*   len  = (const int*)d_in[15];
    float* out = (float*)d_out;

    k1_embed<<<dim3(256, 4), 256>>>(emb, Win, bin, x);
    k2w_conv<<<2048, 256>>>(Wihf, Wihb);
    k2_hmma<<<dim3(128, 16), 256>>>(blf, blb);
    k3_lstm<<<128, 256>>>(Whhf, Whhb, mask);
    k4a_fc<<<256, 256>>>(Wfc, bfc, len);
    k4b_out<<<1, 64>>>(Wout, bout, out);
}

// round 8
// speedup vs baseline: 1.1481x; 1.0407x over previous
#include <cuda_runtime.h>
#include <cuda_bf16.h>
#include <cstdint>

#define B_    32
#define T_    512
#define H_    256
#define WDIM_ 300

typedef unsigned long long u64;

// ---------------- scratch (device globals; no allocation allowed) ----------------
__device__ __align__(16) __nv_bfloat16 g_zhi[16384 * 256];       // z split hi  [r][k]
__device__ __align__(16) __nv_bfloat16 g_zlo[16384 * 256];       // z split lo  [r][k]
__device__ __align__(16) __nv_bfloat16 g_wt[2][2][1024][256];    // [dir][part][c][k]
__device__ __align__(16) float g_gates[2 * 512 * 1024 * 32];     // [dir][t][col][b] 128 MB
__device__ __align__(16) float g_h[2][2][256 * 32];              // [buf][dir][k][b]
__device__ __align__(16) float g_hsum[512 * 32];                 // [feat][b]
__device__ __align__(16) float g_fc[256 * 32];                   // [j][b]
__device__ unsigned g_arrive[2];
__device__ unsigned g_gen[2];
__device__ __align__(128) unsigned g_flags[2][64];               // per-slice publish counters (reset each launch)

// ---------------- f32x2 helpers (exact fp32 semantics) ----------------
__device__ __forceinline__ u64 pk(float lo, float hi) {
    u64 r; asm("mov.b64 %0, {%1, %2};" : "=l"(r) : "f"(lo), "f"(hi)); return r;
}
__device__ __forceinline__ u64 dupf(float v) {
    u64 r; asm("mov.b64 %0, {%1, %1};" : "=l"(r) : "f"(v)); return r;
}
__device__ __forceinline__ void fma2(u64& d, u64 a, u64 b) {
    asm("fma.rn.f32x2 %0, %1, %2, %0;" : "+l"(d) : "l"(a), "l"(b));
}
__device__ __forceinline__ float2 upk(u64 v) {
    float2 f; asm("mov.b64 {%0, %1}, %2;" : "=f"(f.x), "=f"(f.y) : "l"(v)); return f;
}

__device__ __forceinline__ float sigf(float x) { return 1.0f / (1.0f + __expf(-x)); }

__device__ __forceinline__ unsigned ldrelax(const unsigned* p) {
    unsigned v;
    asm volatile("ld.relaxed.gpu.global.u32 %0, [%1];" : "=r"(v) : "l"(p) : "memory");
    return v;
}
__device__ __forceinline__ void fence_acqrel() {
    asm volatile("fence.acq_rel.gpu;" ::: "memory");
}
__device__ __forceinline__ void red_relaxed_add1(unsigned* p) {
    asm volatile("red.relaxed.gpu.global.add.u32 [%0], 1;" :: "l"(p) : "memory");
}

// warp-level bf16 MMA (used by k2)
__device__ __forceinline__ void mma16816(float* c, const unsigned* a, unsigned b0, unsigned b1) {
    asm volatile(
        "mma.sync.aligned.m16n8k16.row.col.f32.bf16.bf16.f32 "
        "{%0,%1,%2,%3}, {%4,%5,%6,%7}, {%8,%9}, {%0,%1,%2,%3};"
        : "+f"(c[0]), "+f"(c[1]), "+f"(c[2]), "+f"(c[3])
        : "r"(a[0]), "r"(a[1]), "r"(a[2]), "r"(a[3]), "r"(b0), "r"(b1));
}

// Sense-reversing barrier among the 64 CTAs of one direction (start + end of k3).
__device__ __forceinline__ void dir_barrier(int dir, unsigned ncta) {
    __syncthreads();
    if (threadIdx.x == 0) {
        volatile unsigned* gen = &g_gen[dir];
        unsigned old = *gen;
        __threadfence();
        unsigned a = atomicAdd(&g_arrive[dir], 1u);
        if (a == ncta - 1u) {
            g_arrive[dir] = 0u;
            __threadfence();
            atomicExch((unsigned*)&g_gen[dir], old + 1u);
        } else {
            while (*gen == old) { }
        }
        __threadfence();
    }
    __syncthreads();
}

// ---------------- kernel 1: z = relu(emb[x] @ W_in + b_in) -> bf16 hi/lo ----------------
__global__ void k1_embed(const float* __restrict__ emb, const float* __restrict__ Win,
                         const float* __restrict__ bin, const int* __restrict__ x) {
    __shared__ float As[12][68];
    __shared__ float Bs[12][68];
    __shared__ int   xid[64];
    int tid = threadIdx.x;
    int r0 = blockIdx.x * 64;
    int c0 = blockIdx.y * 64;
    if (tid < 64) {
        int r = r0 + tid;
        int b = r & 31, t = r >> 5;
        xid[tid] = x[b * T_ + t];
    }
    __syncthreads();
    int tx = tid & 15, ty = tid >> 4;
    u64 acc2[2][4];
#pragma unroll
    for (int p = 0; p < 2; ++p)
#pragma unroll
        for (int j = 0; j < 4; ++j) acc2[p][j] = 0ULL;

    int ar = tid >> 2, ag = (tid & 3) * 3;
    int bc = tid & 63, bg = (tid >> 6) * 3;

    for (int k0 = 0; k0 < WDIM_; k0 += 12) {
        const float* ep = emb + (size_t)xid[ar] * WDIM_ + k0 + ag;
        As[ag + 0][ar] = ep[0];
        As[ag + 1][ar] = ep[1];
        As[ag + 2][ar] = ep[2];
#pragma unroll
        for (int j = 0; j < 3; ++j)
            Bs[bg + j][bc] = Win[(size_t)(k0 + bg + j) * H_ + c0 + bc];
        __syncthreads();
#pragma unroll
        for (int kk = 0; kk < 12; ++kk) {
            float4 a  = *(const float4*)&As[kk][ty * 4];
            float4 bv = *(const float4*)&Bs[kk][tx * 4];
            u64 ap0 = pk(a.x, a.y), ap1 = pk(a.z, a.w);
            u64 bd0 = dupf(bv.x), bd1 = dupf(bv.y), bd2 = dupf(bv.z), bd3 = dupf(bv.w);
            fma2(acc2[0][0], ap0, bd0); fma2(acc2[0][1], ap0, bd1);
            fma2(acc2[0][2], ap0, bd2); fma2(acc2[0][3], ap0, bd3);
            fma2(acc2[1][0], ap1, bd0); fma2(acc2[1][1], ap1, bd1);
            fma2(acc2[1][2], ap1, bd2); fma2(acc2[1][3], ap1, bd3);
        }
        __syncthreads();
    }
    float bj[4];
#pragma unroll
    for (int j = 0; j < 4; ++j) bj[j] = bin[c0 + tx * 4 + j];
#pragma unroll
    for (int p = 0; p < 2; ++p) {
        float2 uu[4];
#pragma unroll
        for (int j = 0; j < 4; ++j) uu[j] = upk(acc2[p][j]);
        float vr[2][4];
#pragma unroll
        for (int j = 0; j < 4; ++j) {
            vr[0][j] = fmaxf(uu[j].x + bj[j], 0.0f);
            vr[1][j] = fmaxf(uu[j].y + bj[j], 0.0f);
        }
#pragma unroll
        for (int q = 0; q < 2; ++q) {
            int r = r0 + ty * 4 + p * 2 + q;
            size_t base = (size_t)r * 256 + c0 + tx * 4;
            __nv_bfloat16 h[4], l[4];
#pragma unroll
            for (int j = 0; j < 4; ++j) {
                h[j] = __float2bfloat16(vr[q][j]);
                l[j] = __float2bfloat16(vr[q][j] - __bfloat162float(h[j]));
            }
            *(__nv_bfloat162*)&g_zhi[base]     = __nv_bfloat162{h[0], h[1]};
            *(__nv_bfloat162*)&g_zhi[base + 2] = __nv_bfloat162{h[2], h[3]};
            *(__nv_bfloat162*)&g_zlo[base]     = __nv_bfloat162{l[0], l[1]};
            *(__nv_bfloat162*)&g_zlo[base + 2] = __nv_bfloat162{l[2], l[3]};
        }
    }
}

// ---------------- kernel 2w: split/transpose Wih -> g_wt[dir][part][c][k] ----------------
__global__ void k2w_conv(const float* __restrict__ Wf, const float* __restrict__ Wb) {
    int gid = blockIdx.x * 256 + threadIdx.x;     // 2*1024*256 total
    int k = gid & 255;
    int c = (gid >> 8) & 1023;
    int dir = gid >> 18;
    float w = (dir ? Wb : Wf)[(size_t)k * 1024 + c];
    __nv_bfloat16 hi = __float2bfloat16(w);
    __nv_bfloat16 lo = __float2bfloat16(w - __bfloat162float(hi));
    g_wt[dir][0][c][k] = hi;
    g_wt[dir][1][c][k] = lo;
}

// ---------------- kernel 2: HMMA bf16-split GEMM: gates = z @ Wih + bl ----------------
#define AS_STRIDE 72
__global__ void __launch_bounds__(256) k2_hmma(const float* __restrict__ blf,
                                               const float* __restrict__ blb) {
    __shared__ __align__(16) unsigned char smraw[2 * 128 * AS_STRIDE * 2];
    __nv_bfloat16* As = (__nv_bfloat16*)smraw;                       // [128][72]
    __nv_bfloat16* Bs = As + 128 * AS_STRIDE;                        // [128][72]
    float* Sc = (float*)smraw;                                       // epilogue: [8 warps][8][33]

    int tid = threadIdx.x;
    int wid = tid >> 5, lane = tid & 31;
    int g = lane >> 2, tg = lane & 3;
    int wm = wid & 3, wn = wid >> 2;
    int bx = blockIdx.x, by = blockIdx.y;
    int dir = by >> 3;
    int c0  = (by & 7) * 128;
    int r0  = bx * 128;

    int lrow = tid >> 1;
    int lhalf = tid & 1;

    float c[2][8][4];
#pragma unroll
    for (int mi = 0; mi < 2; ++mi)
#pragma unroll
        for (int ni = 0; ni < 8; ++ni)
#pragma unroll
            for (int q = 0; q < 4; ++q) c[mi][ni][q] = 0.0f;

    int m0 = wm * 32;
    int n0 = wn * 64;

    for (int seg = 0; seg < 3; ++seg) {
        const __nv_bfloat16* Ag = (seg < 2) ? g_zhi : g_zlo;
        const __nv_bfloat16* Bg = &g_wt[dir][(seg == 1) ? 1 : 0][c0][0];

        for (int chunk = 0; chunk < 4; ++chunk) {
            int k0 = chunk * 64;
            {
                const uint4* src = (const uint4*)(Ag + (size_t)(r0 + lrow) * 256 + k0 + lhalf * 32);
                uint4* dst = (uint4*)(As + lrow * AS_STRIDE + lhalf * 32);
#pragma unroll
                for (int q = 0; q < 4; ++q) dst[q] = src[q];
            }
            {
                const uint4* src = (const uint4*)(Bg + (size_t)lrow * 256 + k0 + lhalf * 32);
                uint4* dst = (uint4*)(Bs + lrow * AS_STRIDE + lhalf * 32);
#pragma unroll
                for (int q = 0; q < 4; ++q) dst[q] = src[q];
            }
            __syncthreads();

#pragma unroll
            for (int ks = 0; ks < 4; ++ks) {
                int k1 = ks * 16;
                unsigned a[2][4];
#pragma unroll
                for (int mi = 0; mi < 2; ++mi) {
                    const __nv_bfloat16* ab = As + (m0 + mi * 16 + g) * AS_STRIDE + k1 + tg * 2;
                    a[mi][0] = *(const unsigned*)ab;
                    a[mi][1] = *(const unsigned*)(ab + 8 * AS_STRIDE);
                    a[mi][2] = *(const unsigned*)(ab + 8);
                    a[mi][3] = *(const unsigned*)(ab + 8 * AS_STRIDE + 8);
                }
#pragma unroll
                for (int ni = 0; ni < 8; ++ni) {
                    const __nv_bfloat16* bb = Bs + (n0 + ni * 8 + g) * AS_STRIDE + k1 + tg * 2;
                    unsigned b0 = *(const unsigned*)bb;
                    unsigned b1 = *(const unsigned*)(bb + 8);
                    mma16816(c[0][ni], a[0], b0, b1);
                    mma16816(c[1][ni], a[1], b0, b1);
                }
            }
            __syncthreads();
        }
    }

    const float* bl = dir ? blb : blf;
    int t = bx * 4 + wm;
    float* myS = Sc + wid * (8 * 33);
    size_t gbase = (size_t)(dir * 512 + t) * (1024 * 32);
#pragma unroll
    for (int ni = 0; ni < 8; ++ni) {
#pragma unroll
        for (int mi = 0; mi < 2; ++mi)
#pragma unroll
            for (int q = 0; q < 4; ++q) {
                int col_local = tg * 2 + (q & 1);
                int row_local = mi * 16 + g + ((q >> 1) ? 8 : 0);
                myS[col_local * 33 + row_local] = c[mi][ni][q];
            }
        __syncwarp();
#pragma unroll
        for (int col = 0; col < 8; ++col) {
            int cg = c0 + n0 + ni * 8 + col;
            float v = myS[col * 33 + lane] + __ldg(&bl[cg]);
            g_gates[gbase + (size_t)cg * 32 + lane] = v;
        }
        __syncwarp();
    }
}

// ---------------- kernel 3: persistent BiLSTM recurrence (fp32 f32x2, per-warp sync) ----------------
// 128 CTAs: dir = cta>>6, slice = cta&63 owns hidden units [slice*4, slice*4+4).
// Warp w consumes K slice [32w,32w+32) -> depends only on producer slices [8w, 8w+8).
// Flags: absolute (reset to 0 at kernel end), quantum 4 per CTA per step.
__global__ void __launch_bounds__(256, 1)
k3_lstm(const float* __restrict__ Whhf, const float* __restrict__ Whhb,
        const int* __restrict__ mask) {
    __shared__ float sm[12288];           // 48 KB
    float* w_s = sm;                      // 4096 floats (persistent Whh slice)
    float* h_s = sm + 4096;               // 8192 floats [k][b]
    float* red = sm + 4096;               // aliased: 8*528 (safe: block syncs separate uses)

    int cta   = blockIdx.x;
    int dir   = cta >> 6;
    int slice = cta & 63;
    int u0    = slice << 2;
    const float* Whh = dir ? Whhb : Whhf;
    int tid  = threadIdx.x;
    int warp = tid >> 5, lane = tid & 31;

    for (int i = tid; i < 4096; i += 256) {
        int k = i >> 4, lc = i & 15;
        w_s[i] = Whh[(size_t)k * 1024 + (lc >> 2) * 256 + u0 + (lc & 3)];
    }

    int u = tid >> 5;        // valid for tid < 128
    int b = tid & 31;
    float c_reg = 0.0f, h_reg = 0.0f, hsum_reg = 0.0f;
    if (tid < 128) g_h[0][dir][(u0 + u) * 32 + b] = 0.0f;

    dir_barrier(dir, 64);    // zeros + w_s visible; flags are 0 (reset by prior launch)

    const unsigned* myflag = &g_flags[dir][(warp << 3) + (lane & 7)];
    unsigned* pubflag = &g_flags[dir][slice];
    int lc4 = (lane & 3) << 2;
    int b4  = (lane >> 2) << 2;
    int kbase = warp << 5;

    for (int t = 0; t < T_; ++t) {
        int cur = t & 1, nxt = cur ^ 1;
        int tt = dir ? (T_ - 1 - t) : t;

        // prefetch gate preactivations + mask (issued before the wait; overlaps spin)
        float gpre0 = 0.f, gpre1 = 0.f, gpre2 = 0.f, gpre3 = 0.f, mval = 0.f;
        if (tid < 128) {
            const float* gp = g_gates + (size_t)(dir * 512 + tt) * (1024 * 32);
            gpre0 = gp[(0 * 256 + u0 + u) * 32 + b];
            gpre1 = gp[(1 * 256 + u0 + u) * 32 + b];
            gpre2 = gp[(2 * 256 + u0 + u) * 32 + b];
            gpre3 = gp[(3 * 256 + u0 + u) * 32 + b];
            mval  = (float)mask[b * T_ + tt];
        }

        // per-warp wait: this warp's 8 producer slices published h(t)
        if (lane < 8) {
            unsigned need = 4u * (unsigned)t;
            while (ldrelax(myflag) < need) { }
        }
        __syncwarp();
        fence_acqrel();

        // per-warp copy of OWN 4KB slice (k rows [kbase, kbase+32)) into h_s
        {
            const uint4* src = ((const uint4*)g_h[cur][dir]) + (kbase << 3);
            uint4* dst = ((uint4*)h_s) + (kbase << 3);
#pragma unroll
            for (int q = 0; q < 8; ++q)
                dst[lane + (q << 5)] = __ldcg(src + lane + (q << 5));
        }
        __syncwarp();

        // z_slice[32][16] partial over this warp's k slice (f32x2-packed)
        u64 acc2[2][4];
#pragma unroll
        for (int p = 0; p < 2; ++p)
#pragma unroll
            for (int j = 0; j < 4; ++j) acc2[p][j] = 0ULL;
#pragma unroll
        for (int kk = 0; kk < 32; ++kk) {
            int k = kbase + kk;
            float4 hv = *(const float4*)&h_s[(k << 5) + b4];
            float4 wv = *(const float4*)&w_s[(k << 4) + lc4];
            u64 hp0 = pk(hv.x, hv.y), hp1 = pk(hv.z, hv.w);
            u64 wd0 = dupf(wv.x), wd1 = dupf(wv.y), wd2 = dupf(wv.z), wd3 = dupf(wv.w);
            fma2(acc2[0][0], hp0, wd0); fma2(acc2[0][1], hp0, wd1);
            fma2(acc2[0][2], hp0, wd2); fma2(acc2[0][3], hp0, wd3);
            fma2(acc2[1][0], hp1, wd0); fma2(acc2[1][1], hp1, wd1);
            fma2(acc2[1][2], hp1, wd2); fma2(acc2[1][3], hp1, wd3);
        }
        __syncthreads();   // sync1: ALL warps done reading h_s before red (alias) writes
#pragma unroll
        for (int p = 0; p < 2; ++p)
#pragma unroll
            for (int j = 0; j < 4; ++j) {
                float2 v = upk(acc2[p][j]);
                red[warp * 528 + (lc4 + j) * 33 + (b4 + 2 * p + 0)] = v.x;
                red[warp * 528 + (lc4 + j) * 33 + (b4 + 2 * p + 1)] = v.y;
            }
        __syncthreads();   // sync2: red complete

        float z0 = gpre0, z1 = gpre1, z2 = gpre2, z3 = gpre3;
        if (tid < 128) {
#pragma unroll
            for (int w = 0; w < 8; ++w) {
                const float* rp = red + w * 528 + b;
                z0 += rp[(0 + u) * 33];
                z1 += rp[(4 + u) * 33];
                z2 += rp[(8 + u) * 33];
                z3 += rp[(12 + u) * 33];
            }
        }
        __syncthreads();   // sync3: red reads done -> non-gate warps free to start next step

        if (tid < 128) {
            float ig = sigf(z0), fg = sigf(z1);
            float gg = tanhf(z2), og = sigf(z3);
            float cn = fg * c_reg + ig * gg;
            float hn = og * tanhf(cn);
            c_reg = mval * cn + (1.0f - mval) * c_reg;
            h_reg = mval * hn + (1.0f - mval) * h_reg;
            hsum_reg += mval * h_reg;
            g_h[nxt][dir][(u0 + u) * 32 + b] = h_reg;
            __syncwarp();
            if (lane == 0) {
                fence_acqrel();            // release: warp's h stores ordered before add
                red_relaxed_add1(pubflag); // +1 per gate warp -> quantum 4 per step
            }
        }
    }
    if (tid < 128) g_hsum[((dir << 8) + u0 + u) * 32 + b] = hsum_reg;

    // reset flags for next launch (all polls/adds done after this barrier)
    dir_barrier(dir, 64);
    if (tid == 0) g_flags[dir][slice] = 0;
}

// ---------------- kernel 4a: fc_hidden[j][b], one CTA per j ----------------
__global__ void k4a_fc(const float* __restrict__ Wfc, const float* __restrict__ bfc,
                       const int* __restrict__ lengths) {
    __shared__ float redsm[8][32];
    int j = blockIdx.x;
    int tid = threadIdx.x;
    int w = tid >> 5, lane = tid & 31;
    float acc = 0.0f;
    int f0 = w * 64;
#pragma unroll 8
    for (int f = f0; f < f0 + 64; ++f)
        acc += g_hsum[f * 32 + lane] * Wfc[(size_t)f * 256 + j];
    redsm[w][lane] = acc;
    __syncthreads();
    if (w == 0) {
        float s = 0.0f;
#pragma unroll
        for (int q = 0; q < 8; ++q) s += redsm[q][lane];
        float invlen = 1.0f / (float)lengths[lane];
        g_fc[j * 32 + lane] = fmaxf(s * invlen + bfc[j], 0.0f);
    }
}

// ---------------- kernel 4b: logits ----------------
__global__ void k4b_out(const float* __restrict__ Wout, const float* __restrict__ bout,
                        float* __restrict__ out) {
    int t = threadIdx.x;
    int b = t >> 1, lab = t & 1;
    float s = bout[lab];
#pragma unroll 8
    for (int j = 0; j < 256; ++j)
        s += g_fc[j * 32 + b] * Wout[j * 2 + lab];
    out[b * 2 + lab] = s;
}

// ---------------- launch ----------------
extern "C" void kernel_launch(void* const* d_in, const int* in_sizes, int n_in,
                              void* d_out, int out_size) {
    const float* emb  = (const float*)d_in[0];
    const float* Win  = (const float*)d_in[1];
    const float* bin  = (const float*)d_in[2];
    const float* Wihf = (const float*)d_in[3];
    const float* Whhf = (const float*)d_in[4];
    const float* blf  = (const float*)d_in[5];
    const float* Wihb = (const float*)d_in[6];
    const float* Whhb = (const float*)d_in[7];
    const float* blb  = (const float*)d_in[8];
    const float* Wfc  = (const float*)d_in[9];
    const float* bfc  = (const float*)d_in[10];
    const float* Wout = (const float*)d_in[11];
    const float* bout = (const float*)d_in[12];
    const int*   x    = (const int*)d_in[13];
    const int*   mask = (const int*)d_in[14];
    const int*   len  = (const int*)d_in[15];
    float* out = (float*)d_out;

    k1_embed<<<dim3(256, 4), 256>>>(emb, Win, bin, x);
    k2w_conv<<<2048, 256>>>(Wihf, Wihb);
    k2_hmma<<<dim3(128, 16), 256>>>(blf, blb);
    k3_lstm<<<128, 256>>>(Whhf, Whhb, mask);
    k4a_fc<<<256, 256>>>(Wfc, bfc, len);
    k4b_out<<<1, 64>>>(Wout, bout, out);
}

// round 9
// speedup vs baseline: 1.7670x; 1.5391x over previous
#include <cuda_runtime.h>
#include <cuda_bf16.h>
#include <cstdint>

#define B_    32
#define T_    512
#define H_    256
#define WDIM_ 300

typedef unsigned long long u64;

// ---------------- scratch (device globals; no allocation allowed) ----------------
__device__ __align__(16) __nv_bfloat16 g_zhi[16384 * 256];       // z split hi  [r][k]
__device__ __align__(16) __nv_bfloat16 g_zlo[16384 * 256];       // z split lo  [r][k]
__device__ __align__(16) __nv_bfloat16 g_wt[2][2][1024][256];    // [dir][part][c][k]
__device__ __align__(16) float g_gates[2 * 512 * 1024 * 32];     // [dir][t][col][b] 128 MB
__device__ __align__(16) float g_h[2][2][256 * 32];              // [buf][dir][k][b]
__device__ __align__(16) float g_hsum[512 * 32];                 // [feat][b]
__device__ __align__(16) float g_fc[256 * 32];                   // [j][b]
__device__ unsigned g_arrive[2];
__device__ unsigned g_gen[2];
__device__ __align__(128) unsigned g_flags[2][64];               // monotonic publish counters

// ---------------- f32x2 helpers (exact fp32 semantics; used in k1) ----------------
__device__ __forceinline__ u64 pk(float lo, float hi) {
    u64 r; asm("mov.b64 %0, {%1, %2};" : "=l"(r) : "f"(lo), "f"(hi)); return r;
}
__device__ __forceinline__ u64 dupf(float v) {
    u64 r; asm("mov.b64 %0, {%1, %1};" : "=l"(r) : "f"(v)); return r;
}
__device__ __forceinline__ void fma2(u64& d, u64 a, u64 b) {
    asm("fma.rn.f32x2 %0, %1, %2, %0;" : "+l"(d) : "l"(a), "l"(b));
}
__device__ __forceinline__ float2 upk(u64 v) {
    float2 f; asm("mov.b64 {%0, %1}, %2;" : "=f"(f.x), "=f"(f.y) : "l"(v)); return f;
}

__device__ __forceinline__ float sigf(float x) { return 1.0f / (1.0f + __expf(-x)); }

__device__ __forceinline__ unsigned ldacq(const unsigned* p) {
    unsigned v;
    asm volatile("ld.acquire.gpu.global.u32 %0, [%1];" : "=r"(v) : "l"(p) : "memory");
    return v;
}
__device__ __forceinline__ void red_release_add1(unsigned* p) {
    asm volatile("red.release.gpu.global.add.u32 [%0], 1;" :: "l"(p) : "memory");
}

// warp-level bf16 MMA (sm_80+ baseline; works on compute_103)
__device__ __forceinline__ void mma16816(float* c, const unsigned* a, unsigned b0, unsigned b1) {
    asm volatile(
        "mma.sync.aligned.m16n8k16.row.col.f32.bf16.bf16.f32 "
        "{%0,%1,%2,%3}, {%4,%5,%6,%7}, {%8,%9}, {%0,%1,%2,%3};"
        : "+f"(c[0]), "+f"(c[1]), "+f"(c[2]), "+f"(c[3])
        : "r"(a[0]), "r"(a[1]), "r"(a[2]), "r"(a[3]), "r"(b0), "r"(b1));
}

// Sense-reversing barrier among the 64 CTAs of one direction (used ONCE at start of k3).
__device__ __forceinline__ void dir_barrier(int dir, unsigned ncta) {
    __syncthreads();
    if (threadIdx.x == 0) {
        volatile unsigned* gen = &g_gen[dir];
        unsigned old = *gen;
        __threadfence();
        unsigned a = atomicAdd(&g_arrive[dir], 1u);
        if (a == ncta - 1u) {
            g_arrive[dir] = 0u;
            __threadfence();
            atomicExch((unsigned*)&g_gen[dir], old + 1u);
        } else {
            while (*gen == old) { }
        }
        __threadfence();
    }
    __syncthreads();
}

// ---------------- kernel 1: z = relu(emb[x] @ W_in + b_in) -> bf16 hi/lo ----------------
__global__ void k1_embed(const float* __restrict__ emb, const float* __restrict__ Win,
                         const float* __restrict__ bin, const int* __restrict__ x) {
    __shared__ float As[12][68];
    __shared__ float Bs[12][68];
    __shared__ int   xid[64];
    int tid = threadIdx.x;
    int r0 = blockIdx.x * 64;
    int c0 = blockIdx.y * 64;
    if (tid < 64) {
        int r = r0 + tid;
        int b = r & 31, t = r >> 5;
        xid[tid] = x[b * T_ + t];
    }
    __syncthreads();
    int tx = tid & 15, ty = tid >> 4;
    u64 acc2[2][4];
#pragma unroll
    for (int p = 0; p < 2; ++p)
#pragma unroll
        for (int j = 0; j < 4; ++j) acc2[p][j] = 0ULL;

    int ar = tid >> 2, ag = (tid & 3) * 3;
    int bc = tid & 63, bg = (tid >> 6) * 3;

    for (int k0 = 0; k0 < WDIM_; k0 += 12) {
        const float* ep = emb + (size_t)xid[ar] * WDIM_ + k0 + ag;
        As[ag + 0][ar] = ep[0];
        As[ag + 1][ar] = ep[1];
        As[ag + 2][ar] = ep[2];
#pragma unroll
        for (int j = 0; j < 3; ++j)
            Bs[bg + j][bc] = Win[(size_t)(k0 + bg + j) * H_ + c0 + bc];
        __syncthreads();
#pragma unroll
        for (int kk = 0; kk < 12; ++kk) {
            float4 a  = *(const float4*)&As[kk][ty * 4];
            float4 bv = *(const float4*)&Bs[kk][tx * 4];
            u64 ap0 = pk(a.x, a.y), ap1 = pk(a.z, a.w);
            u64 bd0 = dupf(bv.x), bd1 = dupf(bv.y), bd2 = dupf(bv.z), bd3 = dupf(bv.w);
            fma2(acc2[0][0], ap0, bd0); fma2(acc2[0][1], ap0, bd1);
            fma2(acc2[0][2], ap0, bd2); fma2(acc2[0][3], ap0, bd3);
            fma2(acc2[1][0], ap1, bd0); fma2(acc2[1][1], ap1, bd1);
            fma2(acc2[1][2], ap1, bd2); fma2(acc2[1][3], ap1, bd3);
        }
        __syncthreads();
    }
    float bj[4];
#pragma unroll
    for (int j = 0; j < 4; ++j) bj[j] = bin[c0 + tx * 4 + j];
#pragma unroll
    for (int p = 0; p < 2; ++p) {
        float2 uu[4];
#pragma unroll
        for (int j = 0; j < 4; ++j) uu[j] = upk(acc2[p][j]);
        float vr[2][4];
#pragma unroll
        for (int j = 0; j < 4; ++j) {
            vr[0][j] = fmaxf(uu[j].x + bj[j], 0.0f);
            vr[1][j] = fmaxf(uu[j].y + bj[j], 0.0f);
        }
#pragma unroll
        for (int q = 0; q < 2; ++q) {
            int r = r0 + ty * 4 + p * 2 + q;
            size_t base = (size_t)r * 256 + c0 + tx * 4;
            __nv_bfloat16 h[4], l[4];
#pragma unroll
            for (int j = 0; j < 4; ++j) {
                h[j] = __float2bfloat16(vr[q][j]);
                l[j] = __float2bfloat16(vr[q][j] - __bfloat162float(h[j]));
            }
            *(__nv_bfloat162*)&g_zhi[base]     = __nv_bfloat162{h[0], h[1]};
            *(__nv_bfloat162*)&g_zhi[base + 2] = __nv_bfloat162{h[2], h[3]};
            *(__nv_bfloat162*)&g_zlo[base]     = __nv_bfloat162{l[0], l[1]};
            *(__nv_bfloat162*)&g_zlo[base + 2] = __nv_bfloat162{l[2], l[3]};
        }
    }
}

// ---------------- kernel 2w: split/transpose Wih -> g_wt[dir][part][c][k] ----------------
__global__ void k2w_conv(const float* __restrict__ Wf, const float* __restrict__ Wb) {
    int gid = blockIdx.x * 256 + threadIdx.x;     // 2*1024*256 total
    int k = gid & 255;
    int c = (gid >> 8) & 1023;
    int dir = gid >> 18;
    float w = (dir ? Wb : Wf)[(size_t)k * 1024 + c];
    __nv_bfloat16 hi = __float2bfloat16(w);
    __nv_bfloat16 lo = __float2bfloat16(w - __bfloat162float(hi));
    g_wt[dir][0][c][k] = hi;
    g_wt[dir][1][c][k] = lo;
}

// ---------------- kernel 2: HMMA bf16-split GEMM: gates = z @ Wih + bl ----------------
#define AS_STRIDE 72
__global__ void __launch_bounds__(256) k2_hmma(const float* __restrict__ blf,
                                               const float* __restrict__ blb) {
    __shared__ __align__(16) unsigned char smraw[2 * 128 * AS_STRIDE * 2];
    __nv_bfloat16* As = (__nv_bfloat16*)smraw;                       // [128][72]
    __nv_bfloat16* Bs = As + 128 * AS_STRIDE;                        // [128][72]
    float* Sc = (float*)smraw;                                       // epilogue: [8 warps][8][33]

    int tid = threadIdx.x;
    int wid = tid >> 5, lane = tid & 31;
    int g = lane >> 2, tg = lane & 3;
    int wm = wid & 3, wn = wid >> 2;
    int bx = blockIdx.x, by = blockIdx.y;
    int dir = by >> 3;
    int c0  = (by & 7) * 128;
    int r0  = bx * 128;

    int lrow = tid >> 1;
    int lhalf = tid & 1;

    float c[2][8][4];
#pragma unroll
    for (int mi = 0; mi < 2; ++mi)
#pragma unroll
        for (int ni = 0; ni < 8; ++ni)
#pragma unroll
            for (int q = 0; q < 4; ++q) c[mi][ni][q] = 0.0f;

    int m0 = wm * 32;
    int n0 = wn * 64;

    for (int seg = 0; seg < 3; ++seg) {
        const __nv_bfloat16* Ag = (seg < 2) ? g_zhi : g_zlo;
        const __nv_bfloat16* Bg = &g_wt[dir][(seg == 1) ? 1 : 0][c0][0];

        for (int chunk = 0; chunk < 4; ++chunk) {
            int k0 = chunk * 64;
            {
                const uint4* src = (const uint4*)(Ag + (size_t)(r0 + lrow) * 256 + k0 + lhalf * 32);
                uint4* dst = (uint4*)(As + lrow * AS_STRIDE + lhalf * 32);
#pragma unroll
                for (int q = 0; q < 4; ++q) dst[q] = src[q];
            }
            {
                const uint4* src = (const uint4*)(Bg + (size_t)lrow * 256 + k0 + lhalf * 32);
                uint4* dst = (uint4*)(Bs + lrow * AS_STRIDE + lhalf * 32);
#pragma unroll
                for (int q = 0; q < 4; ++q) dst[q] = src[q];
            }
            __syncthreads();

#pragma unroll
            for (int ks = 0; ks < 4; ++ks) {
                int k1 = ks * 16;
                unsigned a[2][4];
#pragma unroll
                for (int mi = 0; mi < 2; ++mi) {
                    const __nv_bfloat16* ab = As + (m0 + mi * 16 + g) * AS_STRIDE + k1 + tg * 2;
                    a[mi][0] = *(const unsigned*)ab;
                    a[mi][1] = *(const unsigned*)(ab + 8 * AS_STRIDE);
                    a[mi][2] = *(const unsigned*)(ab + 8);
                    a[mi][3] = *(const unsigned*)(ab + 8 * AS_STRIDE + 8);
                }
#pragma unroll
                for (int ni = 0; ni < 8; ++ni) {
                    const __nv_bfloat16* bb = Bs + (n0 + ni * 8 + g) * AS_STRIDE + k1 + tg * 2;
                    unsigned b0 = *(const unsigned*)bb;
                    unsigned b1 = *(const unsigned*)(bb + 8);
                    mma16816(c[0][ni], a[0], b0, b1);
                    mma16816(c[1][ni], a[1], b0, b1);
                }
            }
            __syncthreads();
        }
    }

    const float* bl = dir ? blb : blf;
    int t = bx * 4 + wm;
    float* myS = Sc + wid * (8 * 33);
    size_t gbase = (size_t)(dir * 512 + t) * (1024 * 32);
#pragma unroll
    for (int ni = 0; ni < 8; ++ni) {
#pragma unroll
        for (int mi = 0; mi < 2; ++mi)
#pragma unroll
            for (int q = 0; q < 4; ++q) {
                int col_local = tg * 2 + (q & 1);
                int row_local = mi * 16 + g + ((q >> 1) ? 8 : 0);
                myS[col_local * 33 + row_local] = c[mi][ni][q];
            }
        __syncwarp();
#pragma unroll
        for (int col = 0; col < 8; ++col) {
            int cg = c0 + n0 + ni * 8 + col;
            float v = myS[col * 33 + lane] + __ldg(&bl[cg]);
            g_gates[gbase + (size_t)cg * 32 + lane] = v;
        }
        __syncwarp();
    }
}

// ---------------- kernel 3: persistent BiLSTM recurrence ----------------
// R5 exchange skeleton (fp32 g_h publish, monotonic 64-flag acquire sync, 4 block
// syncs) with HMMA compute core: consumers convert fp32 h -> bf16 hi/lo (truncation
// split) into As[b][k] during the copy; 24 m16n8k16 per warp; Whh frags in registers.
#define AST   522   // As row stride in bf16 elements (word stride 261)
#define AST_W 261
__global__ void __launch_bounds__(256, 1)
k3_lstm(const float* __restrict__ Whhf, const float* __restrict__ Whhb,
        const int* __restrict__ mask) {
    __shared__ __align__(16) __nv_bfloat16 As[32 * AST];   // 33408 B
    float* red = (float*)As;                               // aliased (8*528 floats)
    unsigned* Asw = (unsigned*)As;

    int cta   = blockIdx.x;
    int dir   = cta >> 6;
    int slice = cta & 63;
    int u0    = slice << 2;
    const float* Whh = dir ? Whhb : Whhf;
    int tid  = threadIdx.x;
    int warp = tid >> 5, lane = tid & 31;
    int g = lane >> 2, tg = lane & 3;
    int kbase = warp << 5;          // warp's K slice [kbase, kbase+32)

    // persistent B fragments (RN split): n = nt*8+g, k = kbase+kt*16+tg*2+r*8
    unsigned bhi[2][2][2], blo[2][2][2];
#pragma unroll
    for (int kt = 0; kt < 2; ++kt)
#pragma unroll
        for (int nt = 0; nt < 2; ++nt)
#pragma unroll
            for (int r = 0; r < 2; ++r) {
                int n  = nt * 8 + g;
                int gc = (n >> 2) * 256 + u0 + (n & 3);
                int k  = kbase + kt * 16 + tg * 2 + r * 8;
                float w0 = Whh[(size_t)k * 1024 + gc];
                float w1 = Whh[(size_t)(k + 1) * 1024 + gc];
                __nv_bfloat16 h0 = __float2bfloat16(w0);
                __nv_bfloat16 h1 = __float2bfloat16(w1);
                __nv_bfloat16 l0 = __float2bfloat16(w0 - __bfloat162float(h0));
                __nv_bfloat16 l1 = __float2bfloat16(w1 - __bfloat162float(h1));
                __nv_bfloat162 ph{h0, h1}, pl{l0, l1};
                bhi[kt][nt][r] = *(unsigned*)&ph;
                blo[kt][nt][r] = *(unsigned*)&pl;
            }

    int u = tid >> 5;        // valid for tid < 128
    int b = tid & 31;
    float c_reg = 0.0f, h_reg = 0.0f, hsum_reg = 0.0f;
    if (tid < 128) g_h[0][dir][(u0 + u) * 32 + b] = 0.0f;

    unsigned base = 0;
    const unsigned* myflag = 0;
    if (tid >= 192) {
        myflag = &g_flags[dir][tid - 192];
        base = ldacq(myflag);
    }
    dir_barrier(dir, 64);    // zeros + base reads complete before any publish

    unsigned* pubflag = &g_flags[dir][slice];
    int kp  = lane >> 3;     // copy: k-pair index 0..3
    int b0c = (lane & 7) * 4;

    for (int t = 0; t < T_; ++t) {
        int cur = t & 1, nxt = cur ^ 1;
        int tt = dir ? (T_ - 1 - t) : t;

        // prefetch gate preactivations + mask (in flight during spin)
        float gpre0 = 0.f, gpre1 = 0.f, gpre2 = 0.f, gpre3 = 0.f, mval = 0.f;
        if (tid < 128) {
            const float* gp = g_gates + (size_t)(dir * 512 + tt) * (1024 * 32);
            gpre0 = gp[(0 * 256 + u0 + u) * 32 + b];
            gpre1 = gp[(1 * 256 + u0 + u) * 32 + b];
            gpre2 = gp[(2 * 256 + u0 + u) * 32 + b];
            gpre3 = gp[(3 * 256 + u0 + u) * 32 + b];
            mval  = (float)mask[b * T_ + tt];
        }

        // wait: all 64 producers published h(t)  (each step adds 128 per flag)
        if (tid >= 192) {
            unsigned need = 128u * (unsigned)t;
            while (ldacq(myflag) - base < need) { }
        }
        __syncthreads();   // syncA: red reads done (prev iter) + h(t) visible

        // copy + convert: warp converts its own 32 k-rows; 4 passes
#pragma unroll
        for (int p = 0; p < 4; ++p) {
            int k = kbase + p * 8 + kp * 2;
            float4 ha = __ldcg((const float4*)&g_h[cur][dir][k * 32 + b0c]);
            float4 hb = __ldcg((const float4*)&g_h[cur][dir][(k + 1) * 32 + b0c]);
            float va[4] = {ha.x, ha.y, ha.z, ha.w};
            float vb[4] = {hb.x, hb.y, hb.z, hb.w};
#pragma unroll
            for (int j = 0; j < 4; ++j) {
                unsigned ba = __float_as_uint(va[j]);
                unsigned bb = __float_as_uint(vb[j]);
                unsigned hiw = __byte_perm(ba, bb, 0x7632);        // (bf16(k), bf16(k+1)) truncated
                float ra = va[j] - __uint_as_float(ba & 0xFFFF0000u);
                float rb = vb[j] - __uint_as_float(bb & 0xFFFF0000u);
                unsigned low;
                asm("cvt.rn.bf16x2.f32 %0, %1, %2;" : "=r"(low) : "f"(rb), "f"(ra));
                int row = b0c + j;
                Asw[row * AST_W + (k >> 1)]       = hiw;
                Asw[row * AST_W + 128 + (k >> 1)] = low;
            }
        }
        __syncthreads();   // syncB

        // 3-term bf16 split MMA over this warp's k slice
        float c[2][2][4];
#pragma unroll
        for (int mi = 0; mi < 2; ++mi)
#pragma unroll
            for (int ni = 0; ni < 2; ++ni)
#pragma unroll
                for (int q = 0; q < 4; ++q) c[mi][ni][q] = 0.0f;

        unsigned afr[2][2][4];
        // A = hi (element offset 0)
#pragma unroll
        for (int kt = 0; kt < 2; ++kt)
#pragma unroll
            for (int mi = 0; mi < 2; ++mi) {
                const __nv_bfloat16* ab = As + (mi * 16 + g) * AST + kbase + kt * 16 + tg * 2;
                afr[kt][mi][0] = *(const unsigned*)ab;
                afr[kt][mi][1] = *(const unsigned*)(ab + 8 * AST);
                afr[kt][mi][2] = *(const unsigned*)(ab + 8);
                afr[kt][mi][3] = *(const unsigned*)(ab + 8 * AST + 8);
            }
#pragma unroll
        for (int kt = 0; kt < 2; ++kt)
#pragma unroll
            for (int mi = 0; mi < 2; ++mi)
#pragma unroll
                for (int ni = 0; ni < 2; ++ni) {
                    mma16816(c[mi][ni], afr[kt][mi], bhi[kt][ni][0], bhi[kt][ni][1]);  // hi*Whi
                    mma16816(c[mi][ni], afr[kt][mi], blo[kt][ni][0], blo[kt][ni][1]);  // hi*Wlo
                }
        // A = lo (element offset 256)
#pragma unroll
        for (int kt = 0; kt < 2; ++kt)
#pragma unroll
            for (int mi = 0; mi < 2; ++mi) {
                const __nv_bfloat16* ab = As + (mi * 16 + g) * AST + 256 + kbase + kt * 16 + tg * 2;
                afr[kt][mi][0] = *(const unsigned*)ab;
                afr[kt][mi][1] = *(const unsigned*)(ab + 8 * AST);
                afr[kt][mi][2] = *(const unsigned*)(ab + 8);
                afr[kt][mi][3] = *(const unsigned*)(ab + 8 * AST + 8);
            }
#pragma unroll
        for (int kt = 0; kt < 2; ++kt)
#pragma unroll
            for (int mi = 0; mi < 2; ++mi)
#pragma unroll
                for (int ni = 0; ni < 2; ++ni)
                    mma16816(c[mi][ni], afr[kt][mi], bhi[kt][ni][0], bhi[kt][ni][1]);  // lo*Whi

        __syncthreads();   // sync1: all fragment reads done before red (alias) writes
#pragma unroll
        for (int mi = 0; mi < 2; ++mi)
#pragma unroll
            for (int ni = 0; ni < 2; ++ni)
#pragma unroll
                for (int q = 0; q < 4; ++q) {
                    int row = mi * 16 + g + ((q >> 1) ? 8 : 0);
                    int col = ni * 8 + tg * 2 + (q & 1);
                    red[warp * 528 + col * 33 + row] = c[mi][ni][q];
                }
        __syncthreads();   // sync2: red complete

        if (tid < 128) {
            float z0 = gpre0, z1 = gpre1, z2 = gpre2, z3 = gpre3;
#pragma unroll
            for (int w = 0; w < 8; ++w) {
                const float* rp = red + w * 528 + b;
                z0 += rp[(0 + u) * 33];
                z1 += rp[(4 + u) * 33];
                z2 += rp[(8 + u) * 33];
                z3 += rp[(12 + u) * 33];
            }
            float ig = sigf(z0), fg = sigf(z1);
            float gg = tanhf(z2), og = sigf(z3);
            float cn = fg * c_reg + ig * gg;
            float hn = og * tanhf(cn);
            c_reg = mval * cn + (1.0f - mval) * c_reg;
            h_reg = mval * hn + (1.0f - mval) * h_reg;
            hsum_reg += mval * h_reg;
            g_h[nxt][dir][(u0 + u) * 32 + b] = h_reg;
            red_release_add1(pubflag);   // release orders this thread's h store
        }
    }
    if (tid < 128) g_hsum[((dir << 8) + u0 + u) * 32 + b] = hsum_reg;
}

// ---------------- kernel 4a: fc_hidden[j][b], one CTA per j ----------------
__global__ void k4a_fc(const float* __restrict__ Wfc, const float* __restrict__ bfc,
                       const int* __restrict__ lengths) {
    __shared__ float redsm[8][32];
    int j = blockIdx.x;
    int tid = threadIdx.x;
    int w = tid >> 5, lane = tid & 31;
    float acc = 0.0f;
    int f0 = w * 64;
#pragma unroll 8
    for (int f = f0; f < f0 + 64; ++f)
        acc += g_hsum[f * 32 + lane] * Wfc[(size_t)f * 256 + j];
    redsm[w][lane] = acc;
    __syncthreads();
    if (w == 0) {
        float s = 0.0f;
#pragma unroll
        for (int q = 0; q < 8; ++q) s += redsm[q][lane];
        float invlen = 1.0f / (float)lengths[lane];
        g_fc[j * 32 + lane] = fmaxf(s * invlen + bfc[j], 0.0f);
    }
}

// ---------------- kernel 4b: logits ----------------
__global__ void k4b_out(const float* __restrict__ Wout, const float* __restrict__ bout,
                        float* __restrict__ out) {
    int t = threadIdx.x;
    int b = t >> 1, lab = t & 1;
    float s = bout[lab];
#pragma unroll 8
    for (int j = 0; j < 256; ++j)
        s += g_fc[j * 32 + b] * Wout[j * 2 + lab];
    out[b * 2 + lab] = s;
}

// ---------------- launch ----------------
extern "C" void kernel_launch(void* const* d_in, const int* in_sizes, int n_in,
                              void* d_out, int out_size) {
    const float* emb  = (const float*)d_in[0];
    const float* Win  = (const float*)d_in[1];
    const float* bin  = (const float*)d_in[2];
    const float* Wihf = (const float*)d_in[3];
    const float* Whhf = (const float*)d_in[4];
    const float* blf  = (const float*)d_in[5];
    const float* Wihb = (const float*)d_in[6];
    const float* Whhb = (const float*)d_in[7];
    const float* blb  = (const float*)d_in[8];
    const float* Wfc  = (const float*)d_in[9];
    const float* bfc  = (const float*)d_in[10];
    const float* Wout = (const float*)d_in[11];
    const float* bout = (const float*)d_in[12];
    const int*   x    = (const int*)d_in[13];
    const int*   mask = (const int*)d_in[14];
    const int*   len  = (const int*)d_in[15];
    float* out = (float*)d_out;

    k1_embed<<<dim3(256, 4), 256>>>(emb, Win, bin, x);
    k2w_conv<<<2048, 256>>>(Wihf, Wihb);
    k2_hmma<<<dim3(128, 16), 256>>>(blf, blb);
    k3_lstm<<<128, 256>>>(Whhf, Whhb, mask);
    k4a_fc<<<256, 256>>>(Wfc, bfc, len);
    k4b_out<<<1, 64>>>(Wout, bout, out);
}